// round 3
// baseline (speedup 1.0000x reference)
#include <cuda_runtime.h>
#include <cstdint>

// Problem constants
#define H      2048
#define W      2048
#define NCOLS  4095          // skewed width = W + H - 1 (columns 0..4094)
#define FC_IN  1024
#define FC_OUT 10
#define NROWS  (H * W / FC_IN)   // 4096 flat rows

// RNN pipeline config
#define NBLK   32            // pipeline stages (blocks), 64 rows each
#define LANES  32
#define RPT    2             // rows per thread
#define CH     16            // columns per chunk
#define NCH    256           // chunks: covers columns 0..4095 (col 4095 computed, unused)

// Scratch (static __device__ — no allocation allowed)
__device__ float g_uns[(size_t)H * W];                 // unskewed activations, 16 MB
__device__ float g_bnd[NBLK][NCH * CH + 64];           // boundary-row stream per block
__device__ volatile int g_flag[NBLK];                  // chunk progress flags

__global__ void init_kernel() {
    if (threadIdx.x < NBLK) g_flag[threadIdx.x] = 0;
}

// tanh(y) where z = y * 2*log2(e):  tanh(y) = 1 - 2/(1 + 2^z)
// ex2/rcp approx are ~2^-22 accurate -> ~1e-6 tanh error (vs 5e-4 for tanh.approx).
__device__ __forceinline__ float tanh_core(float z) {
    float e;
    asm("ex2.approx.f32 %0, %1;" : "=f"(e) : "f"(z));
    float d = e + 1.0f;
    float r;
    asm("rcp.approx.f32 %0, %1;" : "=f"(r) : "f"(d));
    return fmaf(-2.0f, r, 1.0f);
}

// h_new[r] = tanh(k0*h_old[r-1] + k1*h_old[r] + bs + (w*skewed[r,c] + b))
// Block b owns rows [64b, 64b+64). Lane owns rows r0=64b+2*lane, r1=r0+1.
// Neighbor row (r0-1) comes via shfl_up of lane-1's h1; for lane 0 it comes from
// the predecessor block's boundary stream g_bnd[b-1][c-1].
__global__ void __launch_bounds__(32, 1) rnn_kernel(
    const float* __restrict__ x,
    const float* __restrict__ w_in,  const float* __restrict__ b_in,
    const float* __restrict__ w_state, const float* __restrict__ b_state)
{
    const int blk  = blockIdx.x;
    const int lane = threadIdx.x;

    const float LOG2E2 = 2.8853900817779268f;  // 2*log2(e)
    const float k0L = w_state[0] * LOG2E2;
    const float k1L = w_state[1] * LOG2E2;
    const float wL  = w_in[0]    * LOG2E2;
    const float cL  = (b_state[0] + b_in[0]) * LOG2E2;

    const int r0 = blk * (LANES * RPT) + lane * RPT;
    const int r1 = r0 + 1;
    const float* __restrict__ xr0 = x + (size_t)r0 * W;
    const float* __restrict__ xr1 = x + (size_t)r1 * W;
    float* __restrict__ o0 = g_uns + (size_t)r0 * W;
    float* __restrict__ o1 = g_uns + (size_t)r1 * W;

    float h0 = 0.0f, h1 = 0.0f;
    float cin0[CH], cin1[CH];

    // Prefetch + convert chunk 0 inputs. Out-of-range skewed cells are 0
    // (bias still applies: input = 0*w + b -> cin = cL).
    #pragma unroll
    for (int j = 0; j < CH; j++) {
        int i0 = j - r0;
        float v0 = ((unsigned)i0 < W) ? xr0[i0] : 0.0f;
        int i1 = j - r1;
        float v1 = ((unsigned)i1 < W) ? xr1[i1] : 0.0f;
        cin0[j] = fmaf(wL, v0, cL);
        cin1[j] = fmaf(wL, v1, cL);
    }

    for (int k = 0; k < NCH; k++) {
        const int c0 = k * CH;

        // Software-pipeline: issue next chunk's image loads now (latency hidden
        // behind this chunk's ~1000-cycle compute).
        float nv0[CH], nv1[CH];
        if (k + 1 < NCH) {
            const int cn = c0 + CH;
            #pragma unroll
            for (int j = 0; j < CH; j++) {
                int i0 = cn + j - r0;
                nv0[j] = ((unsigned)i0 < W) ? xr0[i0] : 0.0f;
                int i1 = cn + j - r1;
                nv1[j] = ((unsigned)i1 < W) ? xr1[i1] : 0.0f;
            }
        }

        // Acquire predecessor's boundary values h[r0-1, c0-1 .. c0+CH-2]
        // (lane j holds the value needed at column c0+j).
        float bval = 0.0f;
        if (blk > 0) {
            while (g_flag[blk - 1] < k + 1) { }   // volatile spin; all lanes uniform
            __threadfence();                      // acquire
            int bidx = c0 - 1 + lane;
            if (bidx >= 0) bval = g_bnd[blk - 1][bidx];
            // bidx < 0 only at k=0,lane=0: initial state h[-1] = 0.
        }

        #pragma unroll
        for (int j = 0; j < CH; j++) {
            float xn = __shfl_up_sync(0xffffffffu, h1, 1);   // old h[r0-1] (lanes>0)
            float bb = __shfl_sync(0xffffffffu, bval, j);    // boundary for lane 0
            if (lane == 0) xn = bb;
            float t0 = fmaf(k1L, h0, cin0[j]);
            float z0 = fmaf(k0L, xn, t0);
            float t1 = fmaf(k1L, h1, cin1[j]);
            float z1 = fmaf(k0L, h0, t1);   // uses OLD h0 (before update below)
            h0 = tanh_core(z0);
            h1 = tanh_core(z1);

            // Unskew on the fly: unskewed[r, c-r] = acts[c, r]
            int c = c0 + j;
            int i0 = c - r0;
            if ((unsigned)i0 < W) o0[i0] = h0;
            int i1 = c - r1;
            if ((unsigned)i1 < W) o1[i1] = h1;
            // Stream bottom row of this block to the successor
            if (lane == LANES - 1 && blk < NBLK - 1) g_bnd[blk][c] = h1;
        }

        // Release: data stores above -> fence -> flag
        if (blk < NBLK - 1 && lane == LANES - 1) {
            __threadfence();
            g_flag[blk] = k + 1;
        }

        // Convert prefetched inputs for next chunk
        if (k + 1 < NCH) {
            #pragma unroll
            for (int j = 0; j < CH; j++) {
                cin0[j] = fmaf(wL, nv0[j], cL);
                cin1[j] = fmaf(wL, nv1[j], cL);
            }
        }
    }
}

// out[i][j] = sum_k flat[i][k] * fc_w[j][k] + fc_b[j]
// flat = g_uns viewed as [4096, 1024] (row-major, contiguous).
// One warp per flat row; fc_w (40 KB) cached in shared per block.
__global__ void __launch_bounds__(256) fc_kernel(
    const float* __restrict__ fcw, const float* __restrict__ fcb,
    float* __restrict__ out)
{
    __shared__ float ws[FC_OUT * FC_IN];   // 40 KB
    int tid = threadIdx.x;
    for (int i = tid; i < FC_OUT * FC_IN; i += 256) ws[i] = fcw[i];
    __syncthreads();

    int warp = tid >> 5, lane = tid & 31;
    int row = blockIdx.x * 8 + warp;
    const float* xr = g_uns + (size_t)row * FC_IN;

    float xv[32];
    #pragma unroll
    for (int m = 0; m < 32; m++) xv[m] = xr[lane + 32 * m];

    #pragma unroll
    for (int j = 0; j < FC_OUT; j++) {
        float s = 0.0f;
        #pragma unroll
        for (int m = 0; m < 32; m++)
            s = fmaf(xv[m], ws[j * FC_IN + lane + 32 * m], s);
        #pragma unroll
        for (int o = 16; o > 0; o >>= 1)
            s += __shfl_xor_sync(0xffffffffu, s, o);
        if (lane == 0) out[row * FC_OUT + j] = s + fcb[j];
    }
}

extern "C" void kernel_launch(void* const* d_in, const int* in_sizes, int n_in,
                              void* d_out, int out_size)
{
    const float* x       = (const float*)d_in[0];  // [1, 2048, 2048]
    const float* w_in    = (const float*)d_in[1];  // [1,1,1,1]
    const float* b_in    = (const float*)d_in[2];  // [1]
    const float* w_state = (const float*)d_in[3];  // [1,1,2]
    const float* b_state = (const float*)d_in[4];  // [1]
    const float* fc_w    = (const float*)d_in[5];  // [10, 1024]
    const float* fc_b    = (const float*)d_in[6];  // [10]
    float* out = (float*)d_out;                    // [4096, 10]

    // Flags must be reset every launch (graph replays reuse device globals);
    // same-stream ordering guarantees init completes before rnn starts.
    init_kernel<<<1, 32>>>();
    // 32 blocks <= 148 SMs: whole pipeline co-resident in wave 1, spin-waits safe.
    rnn_kernel<<<NBLK, 32>>>(x, w_in, b_in, w_state, b_state);
    fc_kernel<<<NROWS / 8, 256>>>(fc_w, fc_b, out);
}